// round 13
// baseline (speedup 1.0000x reference)
#include <cuda_runtime.h>
#include <cuda_fp16.h>
#include <cstdint>

// ---------------------------------------------------------------------------
// Problem constants
// ---------------------------------------------------------------------------
static constexpr int B_  = 4;
static constexpr int C_  = 64;
static constexpr int H_  = 256;
static constexpr int W_  = 512;
static constexpr int HW  = H_ * W_;               // 131072 = 2^17
static constexpr int SW_ = 3 * W_;                // 1536
static constexpr int TILE_P = 256;                // half image row
static constexpr int TILES_PER_B = HW / TILE_P;   // 512
static constexpr int N_TILES = B_ * TILES_PER_B;  // 2048
static constexpr int THREADS = 256;               // 8 warps, 32 px/warp

// A stages: 256 px rows x 144B pitch (128B data + 16B pad, ldmatrix-friendly)
static constexpr int A_PITCH_B = 144;
static constexpr int A_BYTES   = TILE_P * A_PITCH_B;        // 36864

static constexpr int SMEM_BIAS = 0;                         // 256 B
static constexpr int SMEM_A    = 256;                       // 128-aligned
static constexpr int SMEM_TOTAL = SMEM_A + 2 * A_BYTES;     // 73984 (2 CTAs/SM fit)

__device__ int    g_idx_is64;
__device__ __align__(128) __half g_xt[(size_t)B_ * HW * C_];   // [B][HW][C] fp16
// W records, chunk-major for coalesced warp LDG:
//   halves index = (((j*4 + ks)*4 + c)*32 + lane)*8 + u*2 + lo
__device__ __align__(128) __half g_wrec[9 * 4 * 4 * 32 * 8];   // 73728 B

// ---------------------------------------------------------------------------
// PTX helpers
// ---------------------------------------------------------------------------
__device__ __forceinline__ uint32_t smem_u32(const void* p) {
    uint32_t a;
    asm("{ .reg .u64 t; cvta.to.shared.u64 t, %1; cvt.u32.u64 %0, t; }" : "=r"(a) : "l"(p));
    return a;
}

__device__ __forceinline__ void ldmatrix_x4(uint32_t* r, uint32_t addr) {
    asm volatile("ldmatrix.sync.aligned.m8n8.x4.shared.b16 {%0,%1,%2,%3}, [%4];"
                 : "=r"(r[0]), "=r"(r[1]), "=r"(r[2]), "=r"(r[3]) : "r"(addr));
}

__device__ __forceinline__ void mma_f16(float* c, const uint32_t* a, uint32_t b0, uint32_t b1) {
    asm volatile(
        "mma.sync.aligned.m16n8k16.row.col.f32.f16.f16.f32 "
        "{%0,%1,%2,%3}, {%4,%5,%6,%7}, {%8,%9}, {%0,%1,%2,%3};"
        : "+f"(c[0]), "+f"(c[1]), "+f"(c[2]), "+f"(c[3])
        : "r"(a[0]), "r"(a[1]), "r"(a[2]), "r"(a[3]), "r"(b0), "r"(b1));
}

__device__ __forceinline__ void sts128(uint32_t addr, float4 v) {
    asm volatile("st.shared.v4.b32 [%0], {%1,%2,%3,%4};"
                 :: "r"(addr), "f"(v.x), "f"(v.y), "f"(v.z), "f"(v.w) : "memory");
}

// ---------------------------------------------------------------------------
// Kernel 0: pack W into g_wrec (fp16) — per-lane mma B fragments, chunk-major
// ---------------------------------------------------------------------------
__global__ void wprep_kernel(const float* __restrict__ wgt) {
    int e = blockIdx.x * blockDim.x + threadIdx.x;     // (co*64 + ci)*9 + j order
    if (e >= C_ * C_ * 9) return;
    int ci = (e / 9) & 63, co = e / (9 * 64), j = e % 9;
    int nt = co >> 3, gw = co & 7;
    int ks = ci >> 4, r = ci & 15;
    int bsel = r >> 3, tw = (r & 7) >> 1, lo = r & 1;
    int lane = gw * 4 + tw;
    int c = nt >> 1, u = ((nt & 1) << 1) + bsel;
    g_wrec[((((j * 4 + ks) * 4 + c) * 32 + lane) << 3) + (u << 1) + lo] =
        __float2half_rn(wgt[e]);
}

// ---------------------------------------------------------------------------
// Kernel 1: transpose x [B][C][HW] -> g_xt [B][HW][C] fp16; block (0,0,0)
//           also detects idx dtype (int64 vs int32).
// ---------------------------------------------------------------------------
__global__ void transpose_kernel(const float* __restrict__ x,
                                 const unsigned int* __restrict__ idxw) {
    if (blockIdx.x == 0 && blockIdx.y == 0 && blockIdx.z == 0 &&
        threadIdx.x == 0 && threadIdx.y == 0) {
        int is64 = 1;
        for (int i = 0; i < 64; ++i)
            if (idxw[2 * i + 1] != 0u) { is64 = 0; break; }
        g_idx_is64 = is64;
    }
    __shared__ float t[32][33];
    const int b  = blockIdx.z;
    const int cb = blockIdx.y * 32;
    const int gb = blockIdx.x * 32;
    const int tx = threadIdx.x, ty = threadIdx.y;
    const float* xb = x + (size_t)b * C_ * HW;
#pragma unroll
    for (int i = 0; i < 32; i += 8)
        t[ty + i][tx] = xb[(size_t)(cb + ty + i) * HW + gb + tx];
    __syncthreads();
    __half* xtb = g_xt + ((size_t)b * HW) * C_;
    const int c2  = tx & 15;
    const int sel = tx >> 4;
#pragma unroll
    for (int i = 0; i < 2; ++i) {
        int hwl = ty * 4 + sel * 2 + i;
        __half2 v = __floats2half2_rn(t[2 * c2][hwl], t[2 * c2 + 1][hwl]);
        *(__half2*)(xtb + (size_t)(gb + hwl) * C_ + cb + 2 * c2) = v;
    }
}

// ---------------------------------------------------------------------------
// Kernel 2: persistent fused gather (LDG.128 evict-first + STS.128, 2-stage
//           ring) + fp16 mma.sync; B fragments via coalesced LDG from
//           L1-resident g_wrec.  2 CTAs/SM, 8 warps each, 256 px x 64 co.
// ---------------------------------------------------------------------------
struct Cur { int tile; int tap; };
__device__ __forceinline__ void adv(Cur& c, int stride) {
    if (++c.tap == 9) { c.tap = 0; c.tile += stride; }
}

// gather one 16B chunk: row's idx -> xt row base + 16B lane chunk
__device__ __forceinline__ float4 gather16(const void* idx, int is64,
                                           const Cur& c, int row, int lane7) {
    int pt   = c.tile & (TILES_PER_B - 1);
    int hRow = pt >> 1;
    int wB   = (pt & 1) << 8;
    int kh   = c.tap / 3;
    int kw   = c.tap - kh * 3;
    int o    = (3 * hRow + kh) * SW_ + 3 * (wB + row) + kw;
    int g    = is64 ? (int)__ldcs((const long long*)idx + o)
                    : __ldcs((const int*)idx + o);
    const char* src = (const char*)g_xt
                    + ((((size_t)(c.tile >> 9)) << 17) + (uint32_t)g) * (C_ * 2)
                    + lane7 * 16;
    return __ldcs((const float4*)src);
}

__global__ void __launch_bounds__(THREADS, 2)
latconv_main(const void* __restrict__ idx_raw,
             const float* __restrict__ bias,
             float* __restrict__ out) {
    extern __shared__ char smem[];
    float* bsm = (float*)(smem + SMEM_BIAS);

    const int tid = threadIdx.x;
    const int wid = tid >> 5;       // 0..7
    const int lid = tid & 31;
    const int gid = lid >> 2;       // 0..7
    const int tig = lid & 3;        // 0..3
    const int is64 = g_idx_is64;

    // gather lane mapping: 8 lanes per row -> each warp-LDG.128 covers 4 rows
    const int lane7 = lid & 7;
    const int rbase = wid * 32 + (lid >> 3);   // + k*4 for k = 0..7

    // ldmatrix per-lane address constant (16x16 A tiles, 144B pitch)
    const int lm = lid >> 3, lr = lid & 7;
    const uint32_t lconst = (uint32_t)(((lm & 1) * 8 + lr) * A_PITCH_B
                                       + (lm >> 1) * 16 + wid * 32 * A_PITCH_B);

    if (tid < C_) bsm[tid] = bias[tid];

    const uint32_t abase0 = smem_u32(smem + SMEM_A);
    const uint4* wrec = (const uint4*)g_wrec;   // 16B records, chunk-major

    __syncthreads();

    const int nloc = (N_TILES - (int)blockIdx.x + (int)gridDim.x - 1) / (int)gridDim.x;
    const int S = nloc * 9;
    if (S == 0) return;

    // prologue: fill stage 0 with step-0 data
    Cur c0 = {(int)blockIdx.x, 0};
    {
#pragma unroll
        for (int k = 0; k < 8; ++k) {
            float4 v = gather16(idx_raw, is64, c0, rbase + k * 4, lane7);
            sts128(abase0 + (uint32_t)(rbase + k * 4) * A_PITCH_B + lane7 * 16, v);
        }
    }
    Cur c_iss = c0; adv(c_iss, gridDim.x);     // gathers for step s+1
    Cur c_cmp = {(int)blockIdx.x, 0};

    float acc[2][8][4];

    for (int s = 0; s < S; ++s) {
        __syncthreads();   // stage (s&1) writes visible; stage (s+1)&1 free

        const int  bc   = s & 1;
        const bool have = (s + 1 < S);
        const uint32_t ab = abase0 + bc * A_BYTES;
        const uint32_t an = abase0 + (bc ^ 1) * A_BYTES;

        // batch-A gather LDGs for step s+1 (held in regs through compute)
        float4 stg[4];
        if (have) {
#pragma unroll
            for (int k = 0; k < 4; ++k)
                stg[k] = gather16(idx_raw, is64, c_iss, rbase + k * 4, lane7);
        }

        if (c_cmp.tap == 0) {
#pragma unroll
            for (int mh = 0; mh < 2; ++mh)
#pragma unroll
                for (int nt = 0; nt < 8; ++nt)
#pragma unroll
                    for (int q = 0; q < 4; ++q) acc[mh][nt][q] = 0.f;
        }

        // B record base for this tap: index (((tap*4+ks)*4+c)*32 + lid)
        const int wb = (c_cmp.tap * 16) * 32 + lid;

        // compute ks = 0,1
#pragma unroll
        for (int ks = 0; ks < 2; ++ks) {
            uint32_t a[2][4];
#pragma unroll
            for (int mh = 0; mh < 2; ++mh)
                ldmatrix_x4(a[mh], ab + lconst + mh * (16 * A_PITCH_B) + ks * 32);
#pragma unroll
            for (int c = 0; c < 4; ++c) {
                uint4 q = __ldg(&wrec[wb + (ks * 4 + c) * 32]);
                mma_f16(acc[0][2 * c],     a[0], q.x, q.y);
                mma_f16(acc[1][2 * c],     a[1], q.x, q.y);
                mma_f16(acc[0][2 * c + 1], a[0], q.z, q.w);
                mma_f16(acc[1][2 * c + 1], a[1], q.z, q.w);
            }
        }

        // store batch A, launch batch B
        if (have) {
#pragma unroll
            for (int k = 0; k < 4; ++k)
                sts128(an + (uint32_t)(rbase + k * 4) * A_PITCH_B + lane7 * 16, stg[k]);
#pragma unroll
            for (int k = 0; k < 4; ++k)
                stg[k] = gather16(idx_raw, is64, c_iss, rbase + (k + 4) * 4, lane7);
        }

        // compute ks = 2,3
#pragma unroll
        for (int ks = 2; ks < 4; ++ks) {
            uint32_t a[2][4];
#pragma unroll
            for (int mh = 0; mh < 2; ++mh)
                ldmatrix_x4(a[mh], ab + lconst + mh * (16 * A_PITCH_B) + ks * 32);
#pragma unroll
            for (int c = 0; c < 4; ++c) {
                uint4 q = __ldg(&wrec[wb + (ks * 4 + c) * 32]);
                mma_f16(acc[0][2 * c],     a[0], q.x, q.y);
                mma_f16(acc[1][2 * c],     a[1], q.x, q.y);
                mma_f16(acc[0][2 * c + 1], a[0], q.z, q.w);
                mma_f16(acc[1][2 * c + 1], a[1], q.z, q.w);
            }
        }

        // store batch B
        if (have) {
#pragma unroll
            for (int k = 0; k < 4; ++k)
                sts128(an + (uint32_t)(rbase + (k + 4) * 4) * A_PITCH_B + lane7 * 16, stg[k]);
        }

        if (c_cmp.tap == 8) {
            // epilogue: direct STG from accumulators
            int b  = c_cmp.tile >> 9;
            int pt = c_cmp.tile & (TILES_PER_B - 1);
            int hw0 = (pt >> 1) * W_ + ((pt & 1) << 8);
            float* op = out + ((size_t)b << 23) + hw0;
#pragma unroll
            for (int mh = 0; mh < 2; ++mh) {
                int px = wid * 32 + mh * 16 + gid;
#pragma unroll
                for (int nt = 0; nt < 8; ++nt) {
                    int co = nt * 8 + 2 * tig;
                    float b0 = bsm[co], b1 = bsm[co + 1];
                    float* q = op + (size_t)co * HW + px;
                    q[0]      = acc[mh][nt][0] + b0;
                    q[HW]     = acc[mh][nt][1] + b1;
                    q[8]      = acc[mh][nt][2] + b0;
                    q[HW + 8] = acc[mh][nt][3] + b1;
                }
            }
        }

        adv(c_iss, gridDim.x);
        adv(c_cmp, gridDim.x);
    }
}

// ---------------------------------------------------------------------------
// Launch
// ---------------------------------------------------------------------------
extern "C" void kernel_launch(void* const* d_in, const int* in_sizes, int n_in,
                              void* d_out, int out_size) {
    const float* x    = (const float*)d_in[0];
    const void*  idx  = d_in[1];
    const float* wgt  = (const float*)d_in[2];
    const float* bias = (const float*)d_in[3];
    float* out        = (float*)d_out;

    wprep_kernel<<<(C_ * C_ * 9 + 255) / 256, 256>>>(wgt);

    dim3 tb(32, 8);
    dim3 tg(HW / 32, C_ / 32, B_);
    transpose_kernel<<<tg, tb>>>(x, (const unsigned int*)idx);

    cudaFuncSetAttribute(latconv_main, cudaFuncAttributeMaxDynamicSharedMemorySize,
                         SMEM_TOTAL);
    int sm_count = 0;
    cudaDeviceGetAttribute(&sm_count, cudaDevAttrMultiProcessorCount, 0);
    if (sm_count <= 0) sm_count = 148;

    latconv_main<<<2 * sm_count, THREADS, SMEM_TOTAL>>>(idx, bias, out);
}